// round 2
// baseline (speedup 1.0000x reference)
#include <cuda_runtime.h>

// Problem constants (from reference): B=2, L=1024, M=8, N=16, C=16, H=W=64
#define BB 2
#define LL 1024
#define MM 8
#define NN 16
#define CC 16
#define HH 64
#define WW 64
#define NVOTE (MM * NN)          // 128 votes per (b,l)
#define NBIN  (HH * WW)          // 4096 bins
#define THREADS 256

__global__ __launch_bounds__(THREADS)
void ht_vote_kernel(const float* __restrict__ feats,   // [B,L,N,C]
                    const int*   __restrict__ vsrc,    // [B,L,2] (y,x)
                    const int*   __restrict__ vdst,    // [B,L,2]
                    const int*   __restrict__ isrc,    // [B,L,M]
                    const int*   __restrict__ idst,    // [B,L,N]
                    float*       __restrict__ out)     // [B,L,C,H,W]
{
    __shared__ int   slot_of_bin[NBIN];        // 16 KB: bin -> slot id or -1
    __shared__ float slotw[NVOTE][CC + 1];     // padded to 17 to spread banks
    __shared__ int   vote_slot[NVOTE];
    __shared__ int   s_sh[MM];
    __shared__ int   nslots;

    const int tid = threadIdx.x;
    const int bl  = blockIdx.x;        // b*L + l
    const int b   = bl >> 10;          // L = 1024

    // ---- init shared state ----
    #pragma unroll
    for (int i = tid; i < NBIN; i += THREADS) slot_of_bin[i] = -1;
    #pragma unroll
    for (int i = tid; i < NVOTE * (CC + 1); i += THREADS)
        (&slotw[0][0])[i] = 0.0f;
    if (tid == 0) nslots = 0;
    __syncthreads();

    // ---- Phase A: one thread per vote, compute bin & claim slot ----
    if (tid < NVOTE) {
        const int v = tid;
        const int m = v >> 4;          // N = 16
        const int n = v & 15;

        const int s = isrc[bl * MM + m];
        if (n == 0) s_sh[m] = s;

        const int base_s = b * LL + s;
        const int dd     = idst[base_s * NN + n];
        const int base_d = b * LL + dd;

        const int by = vdst[base_d * 2]     - vsrc[base_s * 2]     + HH / 2;
        const int bx = vdst[base_d * 2 + 1] - vsrc[base_s * 2 + 1] + WW / 2;

        int sl = -1;
        if (by >= 0 && by < HH && bx >= 0 && bx < WW) {
            const int hw = by * WW + bx;
            sl = slot_of_bin[hw];
            if (sl < 0) {
                const int mine = atomicAdd(&nslots, 1);
                const int prev = atomicCAS(&slot_of_bin[hw], -1, mine);
                sl = (prev < 0) ? mine : prev;
            }
        }
        vote_slot[v] = sl;
    }
    __syncthreads();

    // ---- Phase B: accumulate weights (vote, channel) parallel ----
    // 128 votes * 16 channels = 2048 items; 16 consecutive threads share a
    // vote -> each vote's 16-channel feats read is one coalesced 64B chunk.
    #pragma unroll
    for (int i = tid; i < NVOTE * CC; i += THREADS) {
        const int v  = i >> 4;
        const int c  = i & 15;
        const int sl = vote_slot[v];
        if (sl >= 0) {
            const int m = v >> 4;
            const int n = v & 15;
            const float w = feats[((b * LL + s_sh[m]) * NN + n) * CC + c];
            atomicAdd(&slotw[sl][c], w);
        }
    }
    __syncthreads();

    // ---- Phase C: stream the dense [C,H,W] tile to GMEM ----
    // One float4 per thread per (chunk,c); warp writes 512B contiguous.
    float4* out4 = reinterpret_cast<float4*>(out + (size_t)bl * CC * NBIN);
    const int4* sb4 = reinterpret_cast<const int4*>(slot_of_bin);

    #pragma unroll
    for (int chunk = 0; chunk < NBIN / 4 / THREADS; chunk++) {  // 4 chunks
        const int idx4 = chunk * THREADS + tid;   // 0..1023 within a plane
        const int4 sl4 = sb4[idx4];
        #pragma unroll
        for (int c = 0; c < CC; c++) {
            float4 val;
            val.x = (sl4.x >= 0) ? slotw[sl4.x][c] : 0.0f;
            val.y = (sl4.y >= 0) ? slotw[sl4.y][c] : 0.0f;
            val.z = (sl4.z >= 0) ? slotw[sl4.z][c] : 0.0f;
            val.w = (sl4.w >= 0) ? slotw[sl4.w][c] : 0.0f;
            out4[c * (NBIN / 4) + idx4] = val;
        }
    }
}

extern "C" void kernel_launch(void* const* d_in, const int* in_sizes, int n_in,
                              void* d_out, int out_size)
{
    const float* feats = (const float*)d_in[0];   // feats_src_dst [B,L,N,C]
    const int*   vsrc  = (const int*)  d_in[1];   // voxels_src    [B,L,2]
    const int*   vdst  = (const int*)  d_in[2];   // voxels_dst    [B,L,2]
    const int*   isrc  = (const int*)  d_in[3];   // idxs_src      [B,L,M]
    const int*   idst  = (const int*)  d_in[4];   // idxs_dst      [B,L,N]
    float*       out   = (float*)d_out;           // [B,L,C,H,W]

    ht_vote_kernel<<<BB * LL, THREADS>>>(feats, vsrc, vdst, isrc, idst, out);
}

// round 3
// speedup vs baseline: 1.0948x; 1.0948x over previous
#include <cuda_runtime.h>

// Problem constants: B=2, L=1024, M=8, N=16, C=16, H=W=64
#define BB 2
#define LL 1024
#define MM 8
#define NN 16
#define CC 16
#define HH 64
#define WW 64
#define NVOTE (MM * NN)          // 128 votes per (b,l)
#define NBIN  (HH * WW)          // 4096 bins
#define THREADS 256

__global__ __launch_bounds__(THREADS, 4)
void ht_vote_kernel(const float* __restrict__ feats,   // [B,L,N,C]
                    const int*   __restrict__ vsrc,    // [B,L,2] (y,x)
                    const int*   __restrict__ vdst,    // [B,L,2]
                    const int*   __restrict__ isrc,    // [B,L,M]
                    const int*   __restrict__ idst,    // [B,L,N]
                    float*       __restrict__ out)     // [B,L,C,H,W]
{
    __shared__ short slot_of_bin[NBIN];        // 8 KB: bin -> slot id or -1
    __shared__ float slotw[NVOTE][CC + 1];     // padded to 17 to spread banks
    __shared__ short vote_slot[NVOTE];
    __shared__ int   s_sh[MM];
    __shared__ int   nslots;

    const int tid = threadIdx.x;
    const int bl  = blockIdx.x;        // b*L + l
    const int b   = bl >> 10;          // L = 1024

    // ---- init shared state (slot table = 0xFFFF everywhere) ----
    int* sb_i = reinterpret_cast<int*>(slot_of_bin);
    #pragma unroll
    for (int i = tid; i < NBIN / 2; i += THREADS) sb_i[i] = -1;
    #pragma unroll
    for (int i = tid; i < NVOTE * (CC + 1); i += THREADS)
        (&slotw[0][0])[i] = 0.0f;
    if (tid == 0) nslots = 0;
    __syncthreads();

    // ---- Phase A: one thread per vote, compute bin & claim slot ----
    if (tid < NVOTE) {
        const int v = tid;
        const int m = v >> 4;          // N = 16
        const int n = v & 15;

        const int s = isrc[bl * MM + m];
        if (n == 0) s_sh[m] = s;

        const int base_s = b * LL + s;
        const int dd     = idst[base_s * NN + n];
        const int base_d = b * LL + dd;

        const int by = vdst[base_d * 2]     - vsrc[base_s * 2]     + HH / 2;
        const int bx = vdst[base_d * 2 + 1] - vsrc[base_s * 2 + 1] + WW / 2;

        short sl = -1;
        if (by >= 0 && by < HH && bx >= 0 && bx < WW) {
            const int hw = by * WW + bx;
            sl = slot_of_bin[hw];
            if (sl < 0) {
                const int mine = atomicAdd(&nslots, 1);
                const unsigned short prev =
                    atomicCAS(reinterpret_cast<unsigned short*>(&slot_of_bin[hw]),
                              (unsigned short)0xFFFFu, (unsigned short)mine);
                sl = (prev == 0xFFFFu) ? (short)mine : (short)prev;
            }
        }
        vote_slot[v] = sl;
    }
    __syncthreads();

    // ---- Phase B: accumulate weights, (vote, channel) parallel ----
    // 16 consecutive threads share a vote -> coalesced 64B feats reads.
    #pragma unroll
    for (int i = tid; i < NVOTE * CC; i += THREADS) {
        const int v  = i >> 4;
        const int c  = i & 15;
        const int sl = vote_slot[v];
        if (sl >= 0) {
            const int m = v >> 4;
            const int n = v & 15;
            const float w = feats[((b * LL + s_sh[m]) * NN + n) * CC + c];
            atomicAdd(&slotw[sl][c], w);
        }
    }
    __syncthreads();

    // ---- Phase C: stream the dense [C,H,W] tile to GMEM ----
    // One float4 per thread per (chunk,c); warp writes 512B contiguous.
    // Streaming (evict-first) stores: write-once data, don't pollute L2.
    float4* out4 = reinterpret_cast<float4*>(out + (size_t)bl * CC * NBIN);
    const short4* sb4 = reinterpret_cast<const short4*>(slot_of_bin);

    #pragma unroll
    for (int chunk = 0; chunk < NBIN / 4 / THREADS; chunk++) {  // 4 chunks
        const int idx4 = chunk * THREADS + tid;   // 0..1023 within a plane
        const short4 sl4 = sb4[idx4];
        #pragma unroll
        for (int c = 0; c < CC; c++) {
            float4 val;
            val.x = (sl4.x >= 0) ? slotw[sl4.x][c] : 0.0f;
            val.y = (sl4.y >= 0) ? slotw[sl4.y][c] : 0.0f;
            val.z = (sl4.z >= 0) ? slotw[sl4.z][c] : 0.0f;
            val.w = (sl4.w >= 0) ? slotw[sl4.w][c] : 0.0f;
            __stcs(&out4[c * (NBIN / 4) + idx4], val);
        }
    }
}

extern "C" void kernel_launch(void* const* d_in, const int* in_sizes, int n_in,
                              void* d_out, int out_size)
{
    const float* feats = (const float*)d_in[0];   // feats_src_dst [B,L,N,C]
    const int*   vsrc  = (const int*)  d_in[1];   // voxels_src    [B,L,2]
    const int*   vdst  = (const int*)  d_in[2];   // voxels_dst    [B,L,2]
    const int*   isrc  = (const int*)  d_in[3];   // idxs_src      [B,L,M]
    const int*   idst  = (const int*)  d_in[4];   // idxs_dst      [B,L,N]
    float*       out   = (float*)d_out;           // [B,L,C,H,W]

    ht_vote_kernel<<<BB * LL, THREADS>>>(feats, vsrc, vdst, isrc, idst, out);
}